// round 6
// baseline (speedup 1.0000x reference)
#include <cuda_runtime.h>
#include <cuda_fp16.h>
#include <stdint.h>

// out[N,32] = segment_sum_e( edge_val[e] * weight[edge_col[e], :] ) into row edge_row[e], + bias
// Inputs (metadata order) — JAX demotes int64->int32 (x64 disabled):
//   d_in[0] = edge_row  int32  [E]
//   d_in[1] = edge_col  int32  [E]
//   d_in[2] = edge_val  f32    [E]
//   d_in[3] = weight    f32    [N*32]
//   d_in[4] = bias      f32    [32]
// d_out = f32 [N*32]
//
// 3-kernel pipeline, all scratch rebuilt per launch (graph-replay-safe):
//  K1 prep:    weight f32->fp16 cache, out = bias, zero row counters
//  K2 scatter: bucket (col,val) by destination row (CAP=64; overflow -> direct RED)
//  K3 reduce:  warp/row, 4-entry x 8-lane groups, fp16 gathers, one v4 RED per row

static constexpr int D       = 32;
static constexpr int N_NODES = 100000;
static constexpr int CAP     = 64;   // Poisson(16) => P(deg>64) ~ 0; overflow handled anyway

__device__ unsigned long long g_packed[(size_t)N_NODES * CAP];  // (val<<32)|col, 51.2MB
__device__ int    g_counts[N_NODES];
__device__ __half g_wh[(size_t)N_NODES * D];                    // 6.4MB fp16 weights

__device__ __forceinline__ void red_add_v4(float* addr, float4 v) {
    asm volatile("red.global.add.v4.f32 [%0], {%1, %2, %3, %4};"
                 :: "l"(addr), "f"(v.x), "f"(v.y), "f"(v.z), "f"(v.w)
                 : "memory");
}

// ---------------- K1: fused prep ----------------
// w4n == total4 == N*8 for this problem, one grid covers all three jobs.
__global__ void prep_kernel(const float4* __restrict__ w4,
                            const float4* __restrict__ bias4,
                            float4*       __restrict__ out4,
                            int w4n, int total4, int nN) {
    int i = blockIdx.x * blockDim.x + threadIdx.x;
    if (i < w4n) {
        float4 w = w4[i];
        __half2 h0 = __floats2half2_rn(w.x, w.y);
        __half2 h1 = __floats2half2_rn(w.z, w.w);
        uint2 p;
        p.x = *reinterpret_cast<const unsigned*>(&h0);
        p.y = *reinterpret_cast<const unsigned*>(&h1);
        reinterpret_cast<uint2*>(g_wh)[i] = p;
    }
    if (i < total4) {
        out4[i] = bias4[i & 7];
    }
    if (i < nN) {
        g_counts[i] = 0;
    }
}

// ---------------- K2: scatter edges into row buckets ----------------
__global__ void scatter_kernel(const int*   __restrict__ edge_row,
                               const int*   __restrict__ edge_col,
                               const float* __restrict__ edge_val,
                               const float* __restrict__ weight,
                               float*       __restrict__ out,
                               int E) {
    int e = blockIdx.x * blockDim.x + threadIdx.x;
    if (e >= E) return;
    int   r = edge_row[e];
    int   c = edge_col[e];
    float v = edge_val[e];

    int slot = atomicAdd(&g_counts[r], 1);
    if (slot < CAP) {
        unsigned long long cv =
            (unsigned long long)(unsigned)c |
            ((unsigned long long)__float_as_uint(v) << 32);
        g_packed[(size_t)r * CAP + slot] = cv;
    } else {
        // Essentially never taken; full-precision direct reduction.
#pragma unroll
        for (int k = 0; k < D; ++k) {
            atomicAdd(&out[(size_t)r * D + k], v * __ldg(&weight[(size_t)c * D + k]));
        }
    }
}

// ---------------- K3: warp-per-row reduce ----------------
// lane = s*8 + f: s = entry-in-group (4 entries/iter), f = feature chunk (4 feats).
// Per iteration: one broadcast 8B cv load (4 contiguous entries -> 1 sector)
// and one coalesced uint2 fp16 gather. No shfl inside the loop.
__global__ void reduce_kernel(float* __restrict__ out, int N) {
    int lane = threadIdx.x & 31;
    int row  = blockIdx.x * (blockDim.x >> 5) + (threadIdx.x >> 5);
    if (row >= N) return;

    int deg = g_counts[row];
    if (deg > CAP) deg = CAP;

    int s = lane >> 3;       // 0..3: which entry of the group
    int f = lane & 7;        // 0..7: which float4 chunk of the 32 features

    const unsigned long long* base = &g_packed[(size_t)row * CAP];
    const uint2* wh2 = reinterpret_cast<const uint2*>(g_wh);

    float4 acc = make_float4(0.f, 0.f, 0.f, 0.f);
    int groups = (deg + 3) >> 2;
    for (int j = 0; j < groups; ++j) {
        int idx = j * 4 + s;
        if (idx < deg) {
            unsigned long long cv = base[idx];
            int   c = (int)(unsigned)(cv & 0xffffffffull);
            float v = __uint_as_float((unsigned)(cv >> 32));
            uint2 p = __ldg(&wh2[(size_t)c * 8 + f]);
            float2 f0 = __half22float2(*reinterpret_cast<const __half2*>(&p.x));
            float2 f1 = __half22float2(*reinterpret_cast<const __half2*>(&p.y));
            acc.x += v * f0.x;
            acc.y += v * f0.y;
            acc.z += v * f1.x;
            acc.w += v * f1.y;
        }
    }

    // Cross-subgroup reduction: sum over s (xor 8, xor 16).
    acc.x += __shfl_xor_sync(0xffffffffu, acc.x, 8);
    acc.y += __shfl_xor_sync(0xffffffffu, acc.y, 8);
    acc.z += __shfl_xor_sync(0xffffffffu, acc.z, 8);
    acc.w += __shfl_xor_sync(0xffffffffu, acc.w, 8);
    acc.x += __shfl_xor_sync(0xffffffffu, acc.x, 16);
    acc.y += __shfl_xor_sync(0xffffffffu, acc.y, 16);
    acc.z += __shfl_xor_sync(0xffffffffu, acc.z, 16);
    acc.w += __shfl_xor_sync(0xffffffffu, acc.w, 16);

    if (s == 0) {
        // out already holds bias (+ rare overflow REDs); accumulate.
        red_add_v4(&out[(size_t)row * D + f * 4], acc);
    }
}

extern "C" void kernel_launch(void* const* d_in, const int* in_sizes, int n_in,
                              void* d_out, int out_size) {
    const int*    edge_row = (const int*)d_in[0];
    const int*    edge_col = (const int*)d_in[1];
    const float*  edge_val = (const float*)d_in[2];
    const float*  weight   = (const float*)d_in[3];
    const float4* bias4    = (const float4*)d_in[4];
    float*        out      = (float*)d_out;

    const int E      = in_sizes[2];
    const int N      = out_size / D;
    const int total4 = out_size / 4;   // N*8
    const int w4n    = N * D / 4;      // N*8 (same)

    {
        int n = total4 > w4n ? total4 : w4n;
        if (N > n) n = N;
        int threads = 256;
        int blocks  = (n + threads - 1) / threads;
        prep_kernel<<<blocks, threads>>>((const float4*)weight, bias4,
                                         (float4*)out, w4n, total4, N);
    }
    {
        int threads = 256;
        int blocks  = (E + threads - 1) / threads;
        scatter_kernel<<<blocks, threads>>>(edge_row, edge_col, edge_val,
                                            weight, out, E);
    }
    {
        int threads = 256;                 // 8 rows per block
        int blocks  = (N + 7) / 8;
        reduce_kernel<<<blocks, threads>>>(out, N);
    }
}

// round 7
// speedup vs baseline: 1.2390x; 1.2390x over previous
#include <cuda_runtime.h>
#include <cuda_fp16.h>
#include <stdint.h>

// out[N,32] = segment_sum_e( edge_val[e] * weight[edge_col[e], :] ) into row edge_row[e], + bias
// Inputs (metadata order) — JAX demotes int64->int32 (x64 disabled):
//   d_in[0] = edge_row  int32  [E]
//   d_in[1] = edge_col  int32  [E]
//   d_in[2] = edge_val  f32    [E]
//   d_in[3] = weight    f32    [N*32]
//   d_in[4] = bias      f32    [32]
// d_out = f32 [N*32]
//
// 2-kernel pipeline:
//  K1 prep: weight f32->fp16 cache (4x LDG.128 per thread, MLP=4) + out=bias init
//  K2 spmm: 8 lanes/edge, fp16 uint2 gathers, f32 math, v4 f32 global reductions

static constexpr int D       = 32;
static constexpr int N_NODES = 100000;
static constexpr int EDGES_PER_ITER = 4;   // 8 lanes per edge
static constexpr int ITERS_PER_WARP = 4;   // 16 contiguous edges per warp
static constexpr int EDGES_PER_WARP = EDGES_PER_ITER * ITERS_PER_WARP;

__device__ __half g_wh[(size_t)N_NODES * D];   // 6.4 MB fp16 weight cache

__device__ __forceinline__ void red_add_v4(float* addr, float4 v) {
    asm volatile("red.global.add.v4.f32 [%0], {%1, %2, %3, %4};"
                 :: "l"(addr), "f"(v.x), "f"(v.y), "f"(v.z), "f"(v.w)
                 : "memory");
}

__device__ __forceinline__ unsigned pack_h2(float a, float b) {
    __half2 h = __floats2half2_rn(a, b);        // x=a(low), y=b(high)
    return *reinterpret_cast<const unsigned*>(&h);
}

// ---------------- K1: fused prep ----------------
// i < conv16: convert 16 weight floats (4 independent LDG.128) -> uint4 fp16 store.
// i < total4: out4[i] = bias4[i & 7].
__global__ void prep_kernel(const float4* __restrict__ w4,
                            const float4* __restrict__ bias4,
                            float4*       __restrict__ out4,
                            int total4, int conv16) {
    int i = blockIdx.x * blockDim.x + threadIdx.x;
    if (i < conv16) {
        float4 a = w4[4 * i + 0];
        float4 b = w4[4 * i + 1];
        float4 c = w4[4 * i + 2];
        float4 d = w4[4 * i + 3];
        uint4 p0, p1;
        p0.x = pack_h2(a.x, a.y);  p0.y = pack_h2(a.z, a.w);
        p0.z = pack_h2(b.x, b.y);  p0.w = pack_h2(b.z, b.w);
        p1.x = pack_h2(c.x, c.y);  p1.y = pack_h2(c.z, c.w);
        p1.z = pack_h2(d.x, d.y);  p1.w = pack_h2(d.z, d.w);
        uint4* dst = reinterpret_cast<uint4*>(g_wh) + 2 * i;
        dst[0] = p0;
        dst[1] = p1;
    }
    if (i < total4) {
        out4[i] = bias4[i & 7];    // 32 floats = 8 float4
    }
}

// ---------------- K2: spmm, 8 lanes per edge ----------------
// Lane owns 4 features: 8B fp16 gather (uint2), f32 math, 16B v4 RED.
__global__ void spmm_coo_h4_kernel(const int*   __restrict__ edge_row,
                                   const int*   __restrict__ edge_col,
                                   const float* __restrict__ edge_val,
                                   float*       __restrict__ out,
                                   int E) {
    int gtid    = blockIdx.x * blockDim.x + threadIdx.x;
    int warp_id = gtid >> 5;
    int lane    = gtid & 31;
    int sub     = lane >> 3;               // edge within group of 4
    int feat4   = lane & 7;                // which 4-feature chunk

    int e_base = warp_id * EDGES_PER_WARP;
    const uint2* wh2 = reinterpret_cast<const uint2*>(g_wh);

#pragma unroll
    for (int it = 0; it < ITERS_PER_WARP; ++it) {
        int e = e_base + it * EDGES_PER_ITER + sub;
        if (e < E) {
            int   r = edge_row[e];          // 4 distinct values/warp
            int   c = edge_col[e];
            float v = edge_val[e];

            uint2 p = __ldg(&wh2[(size_t)c * 8 + feat4]);   // 8B coalesced
            float2 f0 = __half22float2(*reinterpret_cast<const __half2*>(&p.x));
            float2 f1 = __half22float2(*reinterpret_cast<const __half2*>(&p.y));

            float4 contrib = make_float4(v * f0.x, v * f0.y,
                                         v * f1.x, v * f1.y);
            red_add_v4(&out[(size_t)r * D + feat4 * 4], contrib);
        }
    }
}

extern "C" void kernel_launch(void* const* d_in, const int* in_sizes, int n_in,
                              void* d_out, int out_size) {
    const int*    edge_row = (const int*)d_in[0];
    const int*    edge_col = (const int*)d_in[1];
    const float*  edge_val = (const float*)d_in[2];
    const float*  weight   = (const float*)d_in[3];
    const float4* bias4    = (const float4*)d_in[4];
    float*        out      = (float*)d_out;

    const int E      = in_sizes[2];        // edge count
    const int N      = out_size / D;
    const int total4 = out_size / 4;       // N*8 float4 init stores
    const int conv16 = N * D / 16;         // N*2 convert threads (16 floats each)

    {
        int n = total4 > conv16 ? total4 : conv16;
        int threads = 256;
        int blocks  = (n + threads - 1) / threads;
        prep_kernel<<<blocks, threads>>>((const float4*)weight, bias4,
                                         (float4*)out, total4, conv16);
    }
    {
        int warps   = (E + EDGES_PER_WARP - 1) / EDGES_PER_WARP;
        int threads = 256;                 // 8 warps/block
        int blocks  = (warps + 7) / 8;
        spmm_coo_h4_kernel<<<blocks, threads>>>(edge_row, edge_col, edge_val,
                                                out, E);
    }
}

// round 8
// speedup vs baseline: 1.3529x; 1.0919x over previous
#include <cuda_runtime.h>
#include <stdint.h>

// out[N,32] = segment_sum_e( edge_val[e] * weight[edge_col[e], :] ) into row edge_row[e], + bias
// Inputs (metadata order) — JAX demotes int64->int32 (x64 disabled):
//   d_in[0] = edge_row  int32  [E]
//   d_in[1] = edge_col  int32  [E]
//   d_in[2] = edge_val  f32    [E]
//   d_in[3] = weight    f32    [N*32]
//   d_in[4] = bias      f32    [32]
// d_out = f32 [N*32]
//
// K1: out = bias. K2: spmm, 8 lanes/edge, f32 LDG.128 gathers, v4 f32 REDs.
// Index data loaded once per 32 edges (coalesced, one lane-owned triple) and
// redistributed via SHFL (ALU pipe) to keep the L1tex pipe for gathers+REDs.

static constexpr int D = 32;
static constexpr int ITERS_PER_WARP = 8;   // 4 edges per iteration
static constexpr int EDGES_PER_WARP = 32;  // == warp size: lane owns one edge

__device__ __forceinline__ void red_add_v4(float* addr, float4 v) {
    asm volatile("red.global.add.v4.f32 [%0], {%1, %2, %3, %4};"
                 :: "l"(addr), "f"(v.x), "f"(v.y), "f"(v.z), "f"(v.w)
                 : "memory");
}

__global__ void init_bias_kernel(float4* __restrict__ out4,
                                 const float4* __restrict__ bias4,
                                 int total4) {
    int i = blockIdx.x * blockDim.x + threadIdx.x;
    if (i < total4) {
        out4[i] = bias4[i & 7];            // 32 floats = 8 float4
    }
}

__global__ void spmm_coo_shfl_kernel(const int*    __restrict__ edge_row,
                                     const int*    __restrict__ edge_col,
                                     const float*  __restrict__ edge_val,
                                     const float4* __restrict__ weight4, // [N*8]
                                     float*        __restrict__ out,
                                     int E) {
    int gtid    = blockIdx.x * blockDim.x + threadIdx.x;
    int warp_id = gtid >> 5;
    int lane    = gtid & 31;
    int sub     = lane >> 3;               // edge within group of 4
    int feat4   = lane & 7;                // which float4 chunk of 32 features

    // Each lane owns one edge's metadata: 3 fully-coalesced 128B loads/warp.
    int e_lane = warp_id * EDGES_PER_WARP + lane;
    int   r_own, c_own;
    float v_own;
    if (e_lane < E) {
        r_own = edge_row[e_lane];
        c_own = edge_col[e_lane];
        v_own = edge_val[e_lane];
    } else {
        r_own = 0; c_own = 0; v_own = 0.0f;  // RED of 0.0 -> exact no-op
    }

#pragma unroll
    for (int it = 0; it < ITERS_PER_WARP; ++it) {
        int src = it * 4 + sub;             // lane holding this edge's triple
        int   r = __shfl_sync(0xffffffffu, r_own, src);
        int   c = __shfl_sync(0xffffffffu, c_own, src);
        float v = __shfl_sync(0xffffffffu, v_own, src);

        float4 w = __ldg(&weight4[(size_t)c * 8 + feat4]);   // LDG.128
        float4 contrib = make_float4(v * w.x, v * w.y, v * w.z, v * w.w);
        red_add_v4(&out[(size_t)r * D + feat4 * 4], contrib);
    }
}

extern "C" void kernel_launch(void* const* d_in, const int* in_sizes, int n_in,
                              void* d_out, int out_size) {
    const int*    edge_row = (const int*)d_in[0];
    const int*    edge_col = (const int*)d_in[1];
    const float*  edge_val = (const float*)d_in[2];
    const float4* weight4  = (const float4*)d_in[3];
    const float4* bias4    = (const float4*)d_in[4];
    float*        out      = (float*)d_out;

    const int E      = in_sizes[2];        // edge count
    const int total4 = out_size / 4;       // N * 8

    {
        int threads = 256;
        int blocks  = (total4 + threads - 1) / threads;
        init_bias_kernel<<<blocks, threads>>>((float4*)out, bias4, total4);
    }
    {
        int warps   = (E + EDGES_PER_WARP - 1) / EDGES_PER_WARP;
        int threads = 256;                 // 8 warps/block
        int blocks  = (warps + 7) / 8;
        spmm_coo_shfl_kernel<<<blocks, threads>>>(edge_row, edge_col, edge_val,
                                                  weight4, out, E);
    }
}